// round 7
// baseline (speedup 1.0000x reference)
#include <cuda_runtime.h>
#include <cuda_fp16.h>
#include <math.h>

#define N_NODES 100000
#define N_EDGES 1600000
#define FULL 0xffffffffu
#define NB_SCAN 391   // ceil(100000/256)

// ---- scratch (static device globals; zero at load; layer1 restores zeros) ----
__device__ int   g_count[N_NODES];            // histogram, then absolute scatter cursor
__device__ int   g_rowptr[N_NODES + 1];
__device__ float g_dinv[N_NODES];
__device__ int   g_col[N_EDGES];
__device__ unsigned long long g_bstate[NB_SCAN];  // lookback state (flag<<32 | sum)
__device__ __align__(16) __half g_x0h[N_NODES * 16];  // dinv[v]*x[v]
__device__ __align__(16) __half g_x1h[N_NODES * 64];  // dinv[v]*x1[v]
__device__ __align__(16) __half g_ph [N_NODES * 16];  // dinv[v]*p[v]

// ---------------- 1. histogram (g_count must be zero on entry) ----------------
__global__ void k_hist(const int* __restrict__ ei) {
    int e4 = blockIdx.x * blockDim.x + threadIdx.x;
    if (e4 < N_EDGES / 4) {
        int4 d = ((const int4*)(ei + N_EDGES))[e4];
        atomicAdd(&g_count[d.x], 1);
        atomicAdd(&g_count[d.y], 1);
        atomicAdd(&g_count[d.z], 1);
        atomicAdd(&g_count[d.w], 1);
    }
}

// ---------------- 2. fused scan: rowptr + dinv + cursor + padx ----------------
__global__ void k_scanfused(const float* __restrict__ x) {
    __shared__ int s[256];
    __shared__ int s_prefix;
    const int tid = threadIdx.x;
    const int bid = blockIdx.x;
    const int i = bid * 256 + tid;

    int c = (i < N_NODES) ? g_count[i] : 0;
    s[tid] = c;
    __syncthreads();
    for (int off = 1; off < 256; off <<= 1) {
        int t = (tid >= off) ? s[tid - off] : 0;
        __syncthreads();
        s[tid] += t;
        __syncthreads();
    }
    int total = s[255];

    if (tid == 0) {
        if (bid == 0) {
            s_prefix = 0;
            atomicExch(&g_bstate[0], (2ULL << 32) | (unsigned int)total);
        } else {
            atomicExch(&g_bstate[bid], (1ULL << 32) | (unsigned int)total);
            int pre = 0;
            for (int j = bid - 1; j >= 0; j--) {
                unsigned long long st;
                do {
                    st = *((volatile unsigned long long*)&g_bstate[j]);
                } while ((st >> 32) == 0ULL);
                pre += (int)(st & 0xffffffffULL);
                if ((st >> 32) == 2ULL) break;
            }
            s_prefix = pre;
            atomicExch(&g_bstate[bid], (2ULL << 32) | (unsigned int)(pre + total));
        }
    }
    __syncthreads();

    if (i < N_NODES) {
        int rp = s_prefix + s[tid] - c;   // exclusive prefix
        g_rowptr[i] = rp;
        float di = rsqrtf((float)c + 1.0f);
        g_dinv[i] = di;
        g_count[i] = rp;                  // absolute cursor for scatter
        __half2* o = (__half2*)(g_x0h + i * 16);
#pragma unroll
        for (int q = 0; q < 8; q++) {
            float a = (2 * q < 13)     ? di * x[i * 13 + 2 * q]     : 0.0f;
            float b = (2 * q + 1 < 13) ? di * x[i * 13 + 2 * q + 1] : 0.0f;
            o[q] = __floats2half2_rn(a, b);
        }
    }
    if (i == 0) g_rowptr[N_NODES] = N_EDGES;
}

// ---------------- 3. scatter ----------------
__global__ void k_scatter(const int* __restrict__ ei) {
    int e2 = blockIdx.x * blockDim.x + threadIdx.x;
    if (e2 < N_EDGES / 2) {
        int2 ss = ((const int2*)ei)[e2];
        int2 dd = ((const int2*)(ei + N_EDGES))[e2];
        int p0 = atomicAdd(&g_count[dd.x], 1);
        g_col[p0] = ss.x;
        int p1 = atomicAdd(&g_count[dd.y], 1);
        g_col[p1] = ss.y;
    }
}

// helper: accumulate one fp16x8 (int4) row chunk into 8 fp32 accs
__device__ __forceinline__ void acc8(float* acc, const __half* base) {
    int4 raw = *reinterpret_cast<const int4*>(base);
    float2 f0 = __half22float2(*(__half2*)&raw.x);
    float2 f1 = __half22float2(*(__half2*)&raw.y);
    float2 f2 = __half22float2(*(__half2*)&raw.z);
    float2 f3 = __half22float2(*(__half2*)&raw.w);
    acc[0] += f0.x; acc[1] += f0.y; acc[2] += f1.x; acc[3] += f1.y;
    acc[4] += f2.x; acc[5] += f2.y; acc[6] += f3.x; acc[7] += f3.y;
}

// ---------------- 4. layer 1 (+ zero restore for next replay) ----------------
// block = 8 warps = 8 nodes. Phase A: warp-per-node aggregation.
// Phase B: redistributed GEMM 13->64, weights amortized over 8 nodes.
// x1' = di * relu(di * (agg @ W1) + b1)
__global__ void k_layer1(const float* __restrict__ W1,
                         const float* __restrict__ b1) {
    __shared__ float W1s[13 * 64];
    __shared__ float b1s[64];
    __shared__ float s_x[8][20];
    __shared__ float s_di[8];
    __shared__ __half2 s_oh[8][33];

    {
        int gtid = blockIdx.x * blockDim.x + threadIdx.x;
        if (gtid < N_NODES) g_count[gtid] = 0;
        if (gtid < NB_SCAN) g_bstate[gtid] = 0ULL;
    }
    for (int i = threadIdx.x; i < 13 * 64; i += blockDim.x) W1s[i] = W1[i];
    for (int i = threadIdx.x; i < 64; i += blockDim.x) b1s[i] = b1[i];

    const int warp = threadIdx.x >> 5;
    const int lane = threadIdx.x & 31;
    const int v = blockIdx.x * 8 + warp;
    const int sub = lane & 1, grp = lane >> 1;

    float acc[8] = {0, 0, 0, 0, 0, 0, 0, 0};
    if (grp == 0) acc8(acc, g_x0h + v * 16 + sub * 8);   // self term

    int beg = g_rowptr[v], end = g_rowptr[v + 1];
    for (int t = beg; t < end; t += 32) {
        int i0 = t + grp, i1 = i0 + 16;
        if (i0 < end) acc8(acc, g_x0h + g_col[i0] * 16 + sub * 8);
        if (i1 < end) acc8(acc, g_x0h + g_col[i1] * 16 + sub * 8);
    }
#pragma unroll
    for (int off = 2; off <= 16; off <<= 1)
#pragma unroll
        for (int c = 0; c < 8; c++) acc[c] += __shfl_xor_sync(FULL, acc[c], off);
    if (lane < 2) {
#pragma unroll
        for (int c = 0; c < 8; c++) s_x[warp][sub * 8 + c] = acc[c];
    }
    if (lane == 0) s_di[warp] = g_dinv[v];
    __syncthreads();

    // Phase B: warp w -> outputs [8w, 8w+8) for all 8 nodes
    const int n = lane >> 2, cc = lane & 3;
    const int j0 = 8 * warp + 2 * cc;
    float dx = 0.0f, dy = 0.0f;
#pragma unroll
    for (int k = 0; k < 13; k++) {
        float a = s_x[n][k];
        float2 w = *(const float2*)&W1s[k * 64 + j0];
        dx += a * w.x;
        dy += a * w.y;
    }
    float di = s_di[n];
    float zx = di * dx + b1s[j0];        // FIX: normalize agg before bias/relu
    float zy = di * dy + b1s[j0 + 1];
    s_oh[n][4 * warp + cc] = __floats2half2_rn(di * fmaxf(zx, 0.0f),
                                               di * fmaxf(zy, 0.0f));
    __syncthreads();

    if (lane < 8) {
        __half2 u0 = s_oh[warp][4 * lane + 0];
        __half2 u1 = s_oh[warp][4 * lane + 1];
        __half2 u2 = s_oh[warp][4 * lane + 2];
        __half2 u3 = s_oh[warp][4 * lane + 3];
        int4 pack = make_int4(*(int*)&u0, *(int*)&u1, *(int*)&u2, *(int*)&u3);
        *reinterpret_cast<int4*>(g_x1h + v * 64 + lane * 8) = pack;
    }
}

// ---------------- 5. layer 2 ----------------
// x2 = relu(di*(agg @ W2) + b2) + x1 ; p' = di * (x2 @ W3 + b3-less proj)
__global__ void k_layer2(const float* __restrict__ W2,
                         const float* __restrict__ b2,
                         const float* __restrict__ W3) {
    __shared__ float W2s[64 * 64];
    __shared__ float b2s[64];
    __shared__ float W3s[64 * 10];
    __shared__ float s_agg[8][68];
    __shared__ float s_x2[8][68];
    __shared__ __half2 s_x1h[8][33];
    __shared__ float s_di[8];

    for (int i = threadIdx.x; i < 64 * 64; i += blockDim.x) W2s[i] = W2[i];
    for (int i = threadIdx.x; i < 64; i += blockDim.x) b2s[i] = b2[i];
    for (int i = threadIdx.x; i < 64 * 10; i += blockDim.x) W3s[i] = W3[i];

    const int warp = threadIdx.x >> 5;
    const int lane = threadIdx.x & 31;
    const int v = blockIdx.x * 8 + warp;
    const int sub = lane & 7, grp = lane >> 3;

    float acc[8] = {0, 0, 0, 0, 0, 0, 0, 0};
    if (grp == 0) {
        const __half* self = g_x1h + v * 64 + sub * 8;
        acc8(acc, self);
        int4 raw = *reinterpret_cast<const int4*>(self);
        s_x1h[warp][sub * 4 + 0] = *(__half2*)&raw.x;
        s_x1h[warp][sub * 4 + 1] = *(__half2*)&raw.y;
        s_x1h[warp][sub * 4 + 2] = *(__half2*)&raw.z;
        s_x1h[warp][sub * 4 + 3] = *(__half2*)&raw.w;
    }
    int beg = g_rowptr[v], end = g_rowptr[v + 1];
    for (int t = beg; t < end; t += 16) {
        int i0 = t + grp, i1 = i0 + 4, i2 = i0 + 8, i3 = i0 + 12;
        if (i0 < end) acc8(acc, g_x1h + g_col[i0] * 64 + sub * 8);
        if (i1 < end) acc8(acc, g_x1h + g_col[i1] * 64 + sub * 8);
        if (i2 < end) acc8(acc, g_x1h + g_col[i2] * 64 + sub * 8);
        if (i3 < end) acc8(acc, g_x1h + g_col[i3] * 64 + sub * 8);
    }
#pragma unroll
    for (int off = 8; off <= 16; off <<= 1)
#pragma unroll
        for (int c = 0; c < 8; c++) acc[c] += __shfl_xor_sync(FULL, acc[c], off);
    if (lane < 8) {
#pragma unroll
        for (int c = 0; c < 8; c++) s_agg[warp][sub * 8 + c] = acc[c];
    }
    if (lane == 0) s_di[warp] = g_dinv[v];
    __syncthreads();

    // Phase B
    const int n = lane >> 2, cc = lane & 3;
    const int j0 = 8 * warp + 2 * cc;
    float dx = 0.0f, dy = 0.0f;
#pragma unroll
    for (int k = 0; k < 64; k++) {
        float a = s_agg[n][k];
        float2 w = *(const float2*)&W2s[k * 64 + j0];
        dx += a * w.x;
        dy += a * w.y;
    }
    float di = s_di[n];
    float zx = di * dx + b2s[j0];        // FIX: di on agg only, not bias
    float zy = di * dy + b2s[j0 + 1];
    float rdeg = 1.0f / di;
    float2 r = __half22float2(s_x1h[n][4 * warp + cc]);
    s_x2[n][j0]     = fmaxf(zx, 0.0f) + r.x * rdeg;
    s_x2[n][j0 + 1] = fmaxf(zy, 0.0f) + r.y * rdeg;
    __syncthreads();

    // Phase C: warp-per-node projection 64 -> 10, store p' = di*p (fp16)
    float x2x = s_x2[warp][2 * lane];
    float x2y = s_x2[warp][2 * lane + 1];
    float pj = 0.0f;
#pragma unroll
    for (int j = 0; j < 10; j++) {
        float pv = x2x * W3s[(2 * lane) * 10 + j] + x2y * W3s[(2 * lane + 1) * 10 + j];
        for (int off = 16; off; off >>= 1) pv += __shfl_xor_sync(FULL, pv, off);
        if (lane == j) pj = pv;
    }
    float dw = s_di[warp];
    float phi = __shfl_sync(FULL, pj, (lane + 1) & 31);
    if (lane < 10 && (lane & 1) == 0)
        ((__half2*)(g_ph + v * 16))[lane >> 1] = __floats2half2_rn(dw * pj, dw * phi);
    else if (lane >= 10 && lane < 16 && (lane & 1) == 0)
        ((__half2*)(g_ph + v * 16))[lane >> 1] = __floats2half2_rn(0.0f, 0.0f);
}

// ---------------- 6. layer 3: agg(p')[16h] -> *dinv + b3 -> log_softmax ----------------
__global__ void k_layer3(const float* __restrict__ b3, float* __restrict__ out) {
    __shared__ __align__(16) float sp[8][16];
    int warp = threadIdx.x >> 5;
    int v = blockIdx.x * 8 + warp;
    int lane = threadIdx.x & 31;
    int sub = lane & 1, grp = lane >> 1;

    float acc[8] = {0, 0, 0, 0, 0, 0, 0, 0};
    if (grp == 0) acc8(acc, g_ph + v * 16 + sub * 8);

    int beg = g_rowptr[v], end = g_rowptr[v + 1];
    for (int t = beg; t < end; t += 32) {
        int i0 = t + grp, i1 = i0 + 16;
        if (i0 < end) acc8(acc, g_ph + g_col[i0] * 16 + sub * 8);
        if (i1 < end) acc8(acc, g_ph + g_col[i1] * 16 + sub * 8);
    }
#pragma unroll
    for (int off = 2; off <= 16; off <<= 1)
#pragma unroll
        for (int c = 0; c < 8; c++) acc[c] += __shfl_xor_sync(FULL, acc[c], off);

    if (lane < 2) {
        float4* s4 = (float4*)&sp[warp][sub * 8];
        s4[0] = make_float4(acc[0], acc[1], acc[2], acc[3]);
        s4[1] = make_float4(acc[4], acc[5], acc[6], acc[7]);
    }
    __syncwarp();

    float di = g_dinv[v];
    float z = (lane < 10) ? di * sp[warp][lane] + b3[lane] : -INFINITY;
    float mx = z;
    for (int off = 16; off; off >>= 1) mx = fmaxf(mx, __shfl_xor_sync(FULL, mx, off));
    float ex = (lane < 10) ? expf(z - mx) : 0.0f;
    float s = ex;
    for (int off = 16; off; off >>= 1) s += __shfl_xor_sync(FULL, s, off);
    if (lane < 10) out[v * 10 + lane] = z - mx - logf(s);
}

extern "C" void kernel_launch(void* const* d_in, const int* in_sizes, int n_in,
                              void* d_out, int out_size) {
    const float* x  = (const float*)d_in[0];
    const int*   ei = (const int*)d_in[1];
    const float* W1 = (const float*)d_in[2];
    const float* b1 = (const float*)d_in[3];
    const float* W2 = (const float*)d_in[4];
    const float* b2 = (const float*)d_in[5];
    const float* W3 = (const float*)d_in[6];
    const float* b3 = (const float*)d_in[7];
    float* out = (float*)d_out;

    const int TB = 256;
    int hist4Blocks = (N_EDGES / 4 + TB - 1) / TB;
    int scat2Blocks = (N_EDGES / 2 + TB - 1) / TB;
    int nodeBlocks8 = N_NODES / 8;   // 12500 exactly

    k_hist<<<hist4Blocks, TB>>>(ei);
    k_scanfused<<<NB_SCAN, TB>>>(x);
    k_scatter<<<scat2Blocks, TB>>>(ei);
    k_layer1<<<nodeBlocks8, TB>>>(W1, b1);
    k_layer2<<<nodeBlocks8, TB>>>(W2, b2, W3);
    k_layer3<<<nodeBlocks8, TB>>>(b3, out);
}

// round 8
// speedup vs baseline: 1.0368x; 1.0368x over previous
#include <cuda_runtime.h>
#include <cuda_fp16.h>
#include <math.h>

#define N_NODES 100000
#define N_EDGES 1600000
#define FULL 0xffffffffu
#define NB_SCAN 391        // ceil(100000/256)
#define ZROW N_NODES       // index of the always-zero feature row
#define NGRP 12500         // node groups of 8
#define PBLKS 1184         // persistent blocks for layer1/2 (148 SMs * 8)

// ---- scratch (static device globals; zero at load; layer1 restores zeros) ----
__device__ int   g_count[N_NODES];
__device__ int   g_rowptr[N_NODES + 1];
__device__ float g_dinv[N_NODES];
__device__ int   g_col[N_EDGES + 64];                  // +64 pad: safe tail loads
__device__ unsigned long long g_bstate[NB_SCAN];
__device__ __align__(16) __half g_x0h[(N_NODES + 1) * 16];  // row ZROW stays 0
__device__ __align__(16) __half g_x1h[(N_NODES + 1) * 64];  // row ZROW stays 0
__device__ __align__(16) __half g_ph [(N_NODES + 1) * 16];  // row ZROW + pads stay 0

#define H2(x) (*(__half2*)&(x))

// ---------------- 1. histogram (g_count zero on entry) ----------------
__global__ void k_hist(const int* __restrict__ ei) {
    int e4 = blockIdx.x * blockDim.x + threadIdx.x;
    if (e4 < N_EDGES / 4) {
        int4 d = ((const int4*)(ei + N_EDGES))[e4];
        atomicAdd(&g_count[d.x], 1);
        atomicAdd(&g_count[d.y], 1);
        atomicAdd(&g_count[d.z], 1);
        atomicAdd(&g_count[d.w], 1);
    }
}

// ---------------- 2. fused scan: rowptr + dinv + cursor + padx ----------------
__global__ void k_scanfused(const float* __restrict__ x) {
    __shared__ int s[256];
    __shared__ int s_prefix;
    const int tid = threadIdx.x;
    const int bid = blockIdx.x;
    const int i = bid * 256 + tid;

    int c = (i < N_NODES) ? g_count[i] : 0;
    s[tid] = c;
    __syncthreads();
    for (int off = 1; off < 256; off <<= 1) {
        int t = (tid >= off) ? s[tid - off] : 0;
        __syncthreads();
        s[tid] += t;
        __syncthreads();
    }
    int total = s[255];

    if (tid == 0) {
        if (bid == 0) {
            s_prefix = 0;
            atomicExch(&g_bstate[0], (2ULL << 32) | (unsigned int)total);
        } else {
            atomicExch(&g_bstate[bid], (1ULL << 32) | (unsigned int)total);
            int pre = 0;
            for (int j = bid - 1; j >= 0; j--) {
                unsigned long long st;
                do {
                    st = *((volatile unsigned long long*)&g_bstate[j]);
                } while ((st >> 32) == 0ULL);
                pre += (int)(st & 0xffffffffULL);
                if ((st >> 32) == 2ULL) break;
            }
            s_prefix = pre;
            atomicExch(&g_bstate[bid], (2ULL << 32) | (unsigned int)(pre + total));
        }
    }
    __syncthreads();

    if (i < N_NODES) {
        int rp = s_prefix + s[tid] - c;
        g_rowptr[i] = rp;
        float di = rsqrtf((float)c + 1.0f);
        g_dinv[i] = di;
        g_count[i] = rp;                  // absolute cursor for scatter
        __half2* o = (__half2*)(g_x0h + i * 16);
#pragma unroll
        for (int q = 0; q < 8; q++) {
            float a = (2 * q < 13)     ? di * x[i * 13 + 2 * q]     : 0.0f;
            float b = (2 * q + 1 < 13) ? di * x[i * 13 + 2 * q + 1] : 0.0f;
            o[q] = __floats2half2_rn(a, b);
        }
    }
    if (i == 0) g_rowptr[N_NODES] = N_EDGES;
}

// ---------------- 3. scatter ----------------
__global__ void k_scatter(const int* __restrict__ ei) {
    int e2 = blockIdx.x * blockDim.x + threadIdx.x;
    if (e2 < N_EDGES / 2) {
        int2 ss = ((const int2*)ei)[e2];
        int2 dd = ((const int2*)(ei + N_EDGES))[e2];
        int p0 = atomicAdd(&g_count[dd.x], 1);
        g_col[p0] = ss.x;
        int p1 = atomicAdd(&g_count[dd.y], 1);
        g_col[p1] = ss.y;
    }
}

// fp32 accumulate one int4 (8 halves)
__device__ __forceinline__ void acc8(float* acc, const __half* base) {
    int4 raw = *reinterpret_cast<const int4*>(base);
    float2 f0 = __half22float2(H2(raw.x));
    float2 f1 = __half22float2(H2(raw.y));
    float2 f2 = __half22float2(H2(raw.z));
    float2 f3 = __half22float2(H2(raw.w));
    acc[0] += f0.x; acc[1] += f0.y; acc[2] += f1.x; acc[3] += f1.y;
    acc[4] += f2.x; acc[5] += f2.y; acc[6] += f3.x; acc[7] += f3.y;
}

// fp32 accumulate 4 half2 partial sums
__device__ __forceinline__ void acch(float* acc, __half2 s0, __half2 s1,
                                     __half2 s2, __half2 s3) {
    float2 f0 = __half22float2(s0);
    float2 f1 = __half22float2(s1);
    float2 f2 = __half22float2(s2);
    float2 f3 = __half22float2(s3);
    acc[0] += f0.x; acc[1] += f0.y; acc[2] += f1.x; acc[3] += f1.y;
    acc[4] += f2.x; acc[5] += f2.y; acc[6] += f3.x; acc[7] += f3.y;
}

// ---------------- 4. layer 1 (persistent; + zero restore) ----------------
__global__ void k_layer1(const float* __restrict__ W1,
                         const float* __restrict__ b1) {
    __shared__ float W1s[13 * 64];
    __shared__ float b1s[64];
    __shared__ float s_x[8][20];
    __shared__ float s_di[8];
    __shared__ __half2 s_oh[8][33];

    // zero-restore for next replay (grid-stride, once per launch)
    for (int i = blockIdx.x * 256 + threadIdx.x; i < N_NODES; i += PBLKS * 256)
        g_count[i] = 0;
    for (int i = blockIdx.x * 256 + threadIdx.x; i < NB_SCAN; i += PBLKS * 256)
        g_bstate[i] = 0ULL;
    for (int i = threadIdx.x; i < 13 * 64; i += 256) W1s[i] = W1[i];
    if (threadIdx.x < 64) b1s[threadIdx.x] = b1[threadIdx.x];

    const int warp = threadIdx.x >> 5;
    const int lane = threadIdx.x & 31;
    const int sub = lane & 1, grp = lane >> 1;   // 2 lanes/edge, 16 edges/pass
    const int n = lane >> 2, cc = lane & 3;
    const int j0 = 8 * warp + 2 * cc;

    for (int gg = blockIdx.x; gg < NGRP; gg += PBLKS) {
        __syncthreads();
        const int v = gg * 8 + warp;

        float acc[8] = {0, 0, 0, 0, 0, 0, 0, 0};
        if (grp == 0) acc8(acc, g_x0h + v * 16 + sub * 8);   // self term

        int beg = g_rowptr[v], end = g_rowptr[v + 1];
        for (int t = beg; t < end; t += 32) {
            int i0 = t + grp, i1 = i0 + 16;
            int c0 = (i0 < end) ? g_col[i0] : ZROW;
            int c1 = (i1 < end) ? g_col[i1] : ZROW;
            int4 r0 = *(const int4*)(g_x0h + c0 * 16 + sub * 8);
            int4 r1 = *(const int4*)(g_x0h + c1 * 16 + sub * 8);
            acch(acc,
                 __hadd2(H2(r0.x), H2(r1.x)), __hadd2(H2(r0.y), H2(r1.y)),
                 __hadd2(H2(r0.z), H2(r1.z)), __hadd2(H2(r0.w), H2(r1.w)));
        }
#pragma unroll
        for (int off = 2; off <= 16; off <<= 1)
#pragma unroll
            for (int c = 0; c < 8; c++) acc[c] += __shfl_xor_sync(FULL, acc[c], off);
        if (lane < 2) {
#pragma unroll
            for (int c = 0; c < 8; c++) s_x[warp][sub * 8 + c] = acc[c];
        }
        if (lane == 0) s_di[warp] = g_dinv[v];
        __syncthreads();

        // Phase B: warp w -> outputs [8w, 8w+8) for all 8 nodes
        float dx = 0.0f, dy = 0.0f;
#pragma unroll
        for (int k = 0; k < 13; k++) {
            float a = s_x[n][k];
            float2 w = *(const float2*)&W1s[k * 64 + j0];
            dx += a * w.x;
            dy += a * w.y;
        }
        float di = s_di[n];
        float zx = di * dx + b1s[j0];
        float zy = di * dy + b1s[j0 + 1];
        s_oh[n][4 * warp + cc] = __floats2half2_rn(di * fmaxf(zx, 0.0f),
                                                   di * fmaxf(zy, 0.0f));
        __syncthreads();

        if (lane < 8) {
            __half2 u0 = s_oh[warp][4 * lane + 0];
            __half2 u1 = s_oh[warp][4 * lane + 1];
            __half2 u2 = s_oh[warp][4 * lane + 2];
            __half2 u3 = s_oh[warp][4 * lane + 3];
            int4 pack = make_int4(*(int*)&u0, *(int*)&u1, *(int*)&u2, *(int*)&u3);
            *reinterpret_cast<int4*>(g_x1h + v * 64 + lane * 8) = pack;
        }
    }
}

// ---------------- 5. layer 2 (persistent) ----------------
__global__ void k_layer2(const float* __restrict__ W2,
                         const float* __restrict__ b2,
                         const float* __restrict__ W3) {
    __shared__ float W2s[64 * 64];
    __shared__ float b2s[64];
    __shared__ float W3s[64 * 10];
    __shared__ float s_agg[8][68];
    __shared__ float s_x2[8][68];
    __shared__ __half2 s_x1h[8][33];
    __shared__ float s_di[8];

    for (int i = threadIdx.x; i < 64 * 64; i += 256) W2s[i] = W2[i];
    if (threadIdx.x < 64) b2s[threadIdx.x] = b2[threadIdx.x];
    for (int i = threadIdx.x; i < 64 * 10; i += 256) W3s[i] = W3[i];

    const int warp = threadIdx.x >> 5;
    const int lane = threadIdx.x & 31;
    const int sub = lane & 7, grp = lane >> 3;   // 8 lanes/edge, 4 edges/pass
    const int n = lane >> 2, cc = lane & 3;
    const int j0 = 8 * warp + 2 * cc;

    for (int gg = blockIdx.x; gg < NGRP; gg += PBLKS) {
        __syncthreads();
        const int v = gg * 8 + warp;

        float acc[8] = {0, 0, 0, 0, 0, 0, 0, 0};
        if (grp == 0) {
            const __half* self = g_x1h + v * 64 + sub * 8;
            acc8(acc, self);
            int4 raw = *reinterpret_cast<const int4*>(self);
            s_x1h[warp][sub * 4 + 0] = H2(raw.x);
            s_x1h[warp][sub * 4 + 1] = H2(raw.y);
            s_x1h[warp][sub * 4 + 2] = H2(raw.z);
            s_x1h[warp][sub * 4 + 3] = H2(raw.w);
        }
        int beg = g_rowptr[v], end = g_rowptr[v + 1];
        for (int t = beg; t < end; t += 16) {
            int i0 = t + grp, i1 = i0 + 4, i2 = i0 + 8, i3 = i0 + 12;
            int c0 = (i0 < end) ? g_col[i0] : ZROW;
            int c1 = (i1 < end) ? g_col[i1] : ZROW;
            int c2 = (i2 < end) ? g_col[i2] : ZROW;
            int c3 = (i3 < end) ? g_col[i3] : ZROW;
            int4 r0 = *(const int4*)(g_x1h + c0 * 64 + sub * 8);
            int4 r1 = *(const int4*)(g_x1h + c1 * 64 + sub * 8);
            int4 r2 = *(const int4*)(g_x1h + c2 * 64 + sub * 8);
            int4 r3 = *(const int4*)(g_x1h + c3 * 64 + sub * 8);
            acch(acc,
                 __hadd2(__hadd2(H2(r0.x), H2(r1.x)), __hadd2(H2(r2.x), H2(r3.x))),
                 __hadd2(__hadd2(H2(r0.y), H2(r1.y)), __hadd2(H2(r2.y), H2(r3.y))),
                 __hadd2(__hadd2(H2(r0.z), H2(r1.z)), __hadd2(H2(r2.z), H2(r3.z))),
                 __hadd2(__hadd2(H2(r0.w), H2(r1.w)), __hadd2(H2(r2.w), H2(r3.w))));
        }
#pragma unroll
        for (int off = 8; off <= 16; off <<= 1)
#pragma unroll
            for (int c = 0; c < 8; c++) acc[c] += __shfl_xor_sync(FULL, acc[c], off);
        if (lane < 8) {
#pragma unroll
            for (int c = 0; c < 8; c++) s_agg[warp][sub * 8 + c] = acc[c];
        }
        if (lane == 0) s_di[warp] = g_dinv[v];
        __syncthreads();

        // Phase B: x2 = relu(di*(agg@W2)+b2) + x1
        float dx = 0.0f, dy = 0.0f;
#pragma unroll
        for (int k4 = 0; k4 < 16; k4++) {
            float4 a = *(const float4*)&s_agg[n][4 * k4];
            float2 w0 = *(const float2*)&W2s[(4 * k4 + 0) * 64 + j0];
            float2 w1 = *(const float2*)&W2s[(4 * k4 + 1) * 64 + j0];
            float2 w2 = *(const float2*)&W2s[(4 * k4 + 2) * 64 + j0];
            float2 w3 = *(const float2*)&W2s[(4 * k4 + 3) * 64 + j0];
            dx += a.x * w0.x + a.y * w1.x + a.z * w2.x + a.w * w3.x;
            dy += a.x * w0.y + a.y * w1.y + a.z * w2.y + a.w * w3.y;
        }
        float di = s_di[n];
        float zx = di * dx + b2s[j0];
        float zy = di * dy + b2s[j0 + 1];
        float rdeg = 1.0f / di;
        float2 r = __half22float2(s_x1h[n][4 * warp + cc]);
        s_x2[n][j0]     = fmaxf(zx, 0.0f) + r.x * rdeg;
        s_x2[n][j0 + 1] = fmaxf(zy, 0.0f) + r.y * rdeg;
        __syncthreads();

        // Phase C: 80 threads compute the 80 (node, class) dots; p' = di*p
        if (threadIdx.x < 80) {
            int n2 = threadIdx.x / 10;
            int j  = threadIdx.x - n2 * 10;
            float p = 0.0f;
#pragma unroll
            for (int k4 = 0; k4 < 16; k4++) {
                float4 a = *(const float4*)&s_x2[n2][4 * k4];
                p += a.x * W3s[(4 * k4 + 0) * 10 + j]
                   + a.y * W3s[(4 * k4 + 1) * 10 + j]
                   + a.z * W3s[(4 * k4 + 2) * 10 + j]
                   + a.w * W3s[(4 * k4 + 3) * 10 + j];
            }
            g_ph[(gg * 8 + n2) * 16 + j] = __float2half(s_di[n2] * p);
        }
        // pads g_ph[.][10..15] never written -> stay zero (BSS)
    }
}

// ---------------- 6. layer 3: agg(p')[16h] -> *dinv + b3 -> log_softmax ----------------
__global__ void k_layer3(const float* __restrict__ b3, float* __restrict__ out) {
    __shared__ __align__(16) float sp[8][16];
    int warp = threadIdx.x >> 5;
    int v = blockIdx.x * 8 + warp;
    int lane = threadIdx.x & 31;
    int sub = lane & 1, grp = lane >> 1;

    float acc[8] = {0, 0, 0, 0, 0, 0, 0, 0};
    if (grp == 0) acc8(acc, g_ph + v * 16 + sub * 8);

    int beg = g_rowptr[v], end = g_rowptr[v + 1];
    for (int t = beg; t < end; t += 32) {
        int i0 = t + grp, i1 = i0 + 16;
        int c0 = (i0 < end) ? g_col[i0] : ZROW;
        int c1 = (i1 < end) ? g_col[i1] : ZROW;
        int4 r0 = *(const int4*)(g_ph + c0 * 16 + sub * 8);
        int4 r1 = *(const int4*)(g_ph + c1 * 16 + sub * 8);
        acch(acc,
             __hadd2(H2(r0.x), H2(r1.x)), __hadd2(H2(r0.y), H2(r1.y)),
             __hadd2(H2(r0.z), H2(r1.z)), __hadd2(H2(r0.w), H2(r1.w)));
    }
#pragma unroll
    for (int off = 2; off <= 16; off <<= 1)
#pragma unroll
        for (int c = 0; c < 8; c++) acc[c] += __shfl_xor_sync(FULL, acc[c], off);

    if (lane < 2) {
        float4* s4 = (float4*)&sp[warp][sub * 8];
        s4[0] = make_float4(acc[0], acc[1], acc[2], acc[3]);
        s4[1] = make_float4(acc[4], acc[5], acc[6], acc[7]);
    }
    __syncwarp();

    float di = g_dinv[v];
    float z = (lane < 10) ? di * sp[warp][lane] + b3[lane] : -INFINITY;
    float mx = z;
    for (int off = 16; off; off >>= 1) mx = fmaxf(mx, __shfl_xor_sync(FULL, mx, off));
    float ex = (lane < 10) ? expf(z - mx) : 0.0f;
    float s = ex;
    for (int off = 16; off; off >>= 1) s += __shfl_xor_sync(FULL, s, off);
    if (lane < 10) out[v * 10 + lane] = z - mx - logf(s);
}

extern "C" void kernel_launch(void* const* d_in, const int* in_sizes, int n_in,
                              void* d_out, int out_size) {
    const float* x  = (const float*)d_in[0];
    const int*   ei = (const int*)d_in[1];
    const float* W1 = (const float*)d_in[2];
    const float* b1 = (const float*)d_in[3];
    const float* W2 = (const float*)d_in[4];
    const float* b2 = (const float*)d_in[5];
    const float* W3 = (const float*)d_in[6];
    const float* b3 = (const float*)d_in[7];
    float* out = (float*)d_out;

    const int TB = 256;
    int hist4Blocks = (N_EDGES / 4 + TB - 1) / TB;
    int scat2Blocks = (N_EDGES / 2 + TB - 1) / TB;

    k_hist<<<hist4Blocks, TB>>>(ei);
    k_scanfused<<<NB_SCAN, TB>>>(x);
    k_scatter<<<scat2Blocks, TB>>>(ei);
    k_layer1<<<PBLKS, TB>>>(W1, b1);
    k_layer2<<<PBLKS, TB>>>(W2, b2, W3);
    k_layer3<<<NGRP, TB>>>(b3, out);
}

// round 9
// speedup vs baseline: 1.1736x; 1.1319x over previous
#include <cuda_runtime.h>
#include <cuda_fp16.h>
#include <math.h>

#define N_NODES 100000
#define N_EDGES 1600000
#define FULL 0xffffffffu
#define NB_SCAN 391        // ceil(100000/256)
#define ZROW N_NODES       // index of the always-zero feature row
#define NGRP 12500         // node groups of 8
#define PBLKS 1184         // persistent blocks for layer2 (148 SMs * 8)

// ---- scratch (static device globals; zero at load; layer1 restores zeros) ----
__device__ int   g_count[N_NODES];
__device__ int   g_rowptr[N_NODES + 1];
__device__ float g_dinv[N_NODES];
__device__ int   g_col[N_EDGES + 64];                  // +64 pad: safe tail loads
__device__ unsigned long long g_bstate[NB_SCAN];
__device__ __align__(16) __half g_x0h[(N_NODES + 1) * 16];  // row ZROW stays 0
__device__ __align__(16) __half g_x1h[(N_NODES + 1) * 64];  // row ZROW stays 0
__device__ __align__(16) __half g_ph [(N_NODES + 1) * 16];  // row ZROW + pads stay 0

#define H2(x) (*(__half2*)&(x))

// ---------------- 1. histogram (g_count zero on entry) ----------------
__global__ void k_hist(const int* __restrict__ ei) {
    int e4 = blockIdx.x * blockDim.x + threadIdx.x;
    if (e4 < N_EDGES / 4) {
        int4 d = ((const int4*)(ei + N_EDGES))[e4];
        atomicAdd(&g_count[d.x], 1);
        atomicAdd(&g_count[d.y], 1);
        atomicAdd(&g_count[d.z], 1);
        atomicAdd(&g_count[d.w], 1);
    }
}

// ---------------- 2. fused scan: rowptr + dinv + cursor + padx ----------------
__global__ void k_scanfused(const float* __restrict__ x) {
    __shared__ int s[256];
    __shared__ int s_prefix;
    const int tid = threadIdx.x;
    const int bid = blockIdx.x;
    const int i = bid * 256 + tid;

    int c = (i < N_NODES) ? g_count[i] : 0;
    s[tid] = c;
    __syncthreads();
    for (int off = 1; off < 256; off <<= 1) {
        int t = (tid >= off) ? s[tid - off] : 0;
        __syncthreads();
        s[tid] += t;
        __syncthreads();
    }
    int total = s[255];

    if (tid == 0) {
        if (bid == 0) {
            s_prefix = 0;
            atomicExch(&g_bstate[0], (2ULL << 32) | (unsigned int)total);
        } else {
            atomicExch(&g_bstate[bid], (1ULL << 32) | (unsigned int)total);
            int pre = 0;
            for (int j = bid - 1; j >= 0; j--) {
                unsigned long long st;
                do {
                    st = *((volatile unsigned long long*)&g_bstate[j]);
                } while ((st >> 32) == 0ULL);
                pre += (int)(st & 0xffffffffULL);
                if ((st >> 32) == 2ULL) break;
            }
            s_prefix = pre;
            atomicExch(&g_bstate[bid], (2ULL << 32) | (unsigned int)(pre + total));
        }
    }
    __syncthreads();

    if (i < N_NODES) {
        int rp = s_prefix + s[tid] - c;
        g_rowptr[i] = rp;
        float di = rsqrtf((float)c + 1.0f);
        g_dinv[i] = di;
        g_count[i] = rp;                  // absolute cursor for scatter
        __half2* o = (__half2*)(g_x0h + i * 16);
#pragma unroll
        for (int q = 0; q < 8; q++) {
            float a = (2 * q < 13)     ? di * x[i * 13 + 2 * q]     : 0.0f;
            float b = (2 * q + 1 < 13) ? di * x[i * 13 + 2 * q + 1] : 0.0f;
            o[q] = __floats2half2_rn(a, b);
        }
    }
    if (i == 0) g_rowptr[N_NODES] = N_EDGES;
}

// ---------------- 3. scatter ----------------
__global__ void k_scatter(const int* __restrict__ ei) {
    int e2 = blockIdx.x * blockDim.x + threadIdx.x;
    if (e2 < N_EDGES / 2) {
        int2 ss = ((const int2*)ei)[e2];
        int2 dd = ((const int2*)(ei + N_EDGES))[e2];
        int p0 = atomicAdd(&g_count[dd.x], 1);
        g_col[p0] = ss.x;
        int p1 = atomicAdd(&g_count[dd.y], 1);
        g_col[p1] = ss.y;
    }
}

// fp32 accumulate one int4 (8 halves)
__device__ __forceinline__ void acc8(float* acc, const __half* base) {
    int4 raw = *reinterpret_cast<const int4*>(base);
    float2 f0 = __half22float2(H2(raw.x));
    float2 f1 = __half22float2(H2(raw.y));
    float2 f2 = __half22float2(H2(raw.z));
    float2 f3 = __half22float2(H2(raw.w));
    acc[0] += f0.x; acc[1] += f0.y; acc[2] += f1.x; acc[3] += f1.y;
    acc[4] += f2.x; acc[5] += f2.y; acc[6] += f3.x; acc[7] += f3.y;
}

// fp32 accumulate 4 half2 partial sums
__device__ __forceinline__ void acch(float* acc, __half2 s0, __half2 s1,
                                     __half2 s2, __half2 s3) {
    float2 f0 = __half22float2(s0);
    float2 f1 = __half22float2(s1);
    float2 f2 = __half22float2(s2);
    float2 f3 = __half22float2(s3);
    acc[0] += f0.x; acc[1] += f0.y; acc[2] += f1.x; acc[3] += f1.y;
    acc[4] += f2.x; acc[5] += f2.y; acc[6] += f3.x; acc[7] += f3.y;
}

// fp32 accumulate 2 half2 partial sums (4 floats)
__device__ __forceinline__ void acch4(float* acc, __half2 s0, __half2 s1) {
    float2 f0 = __half22float2(s0);
    float2 f1 = __half22float2(s1);
    acc[0] += f0.x; acc[1] += f0.y; acc[2] += f1.x; acc[3] += f1.y;
}

// ---------------- 4. layer 1 (non-persistent; + zero restore) ----------------
// block = 8 warps = 8 nodes. Phase A: 4 lanes/edge (int2), 8 edge groups,
// 16 edges/pass, 12-shfl reduction. Phase B: redistributed GEMM 13->64.
__global__ void k_layer1(const float* __restrict__ W1,
                         const float* __restrict__ b1) {
    __shared__ float W1s[13 * 64];
    __shared__ float b1s[64];
    __shared__ float s_x[8][20];
    __shared__ float s_di[8];
    __shared__ __half2 s_oh[8][33];

    {
        int gtid = blockIdx.x * 256 + threadIdx.x;
        if (gtid < N_NODES) g_count[gtid] = 0;
        if (gtid < NB_SCAN) g_bstate[gtid] = 0ULL;
    }
    for (int i = threadIdx.x; i < 13 * 64; i += 256) W1s[i] = W1[i];
    if (threadIdx.x < 64) b1s[threadIdx.x] = b1[threadIdx.x];

    const int warp = threadIdx.x >> 5;
    const int lane = threadIdx.x & 31;
    const int v = blockIdx.x * 8 + warp;
    const int sub = lane & 3, grp = lane >> 2;   // 4 lanes/edge, 8 groups

    float acc[4] = {0, 0, 0, 0};
    if (grp == 0) {
        int2 raw = *(const int2*)(g_x0h + v * 16 + sub * 4);
        acch4(acc, H2(raw.x), H2(raw.y));
    }
    int beg = g_rowptr[v], end = g_rowptr[v + 1];
    for (int t = beg; t < end; t += 16) {
        int i0 = t + grp, i1 = i0 + 8;
        int c0 = (i0 < end) ? g_col[i0] : ZROW;
        int c1 = (i1 < end) ? g_col[i1] : ZROW;
        int2 r0 = *(const int2*)(g_x0h + c0 * 16 + sub * 4);
        int2 r1 = *(const int2*)(g_x0h + c1 * 16 + sub * 4);
        acch4(acc, __hadd2(H2(r0.x), H2(r1.x)), __hadd2(H2(r0.y), H2(r1.y)));
    }
#pragma unroll
    for (int off = 4; off <= 16; off <<= 1)
#pragma unroll
        for (int c = 0; c < 4; c++) acc[c] += __shfl_xor_sync(FULL, acc[c], off);
    if (lane < 4)
        *(float4*)&s_x[warp][lane * 4] = make_float4(acc[0], acc[1], acc[2], acc[3]);
    if (lane == 0) s_di[warp] = g_dinv[v];
    __syncthreads();

    // Phase B: warp w -> outputs [8w, 8w+8) for all 8 nodes
    const int n = lane >> 2, cc = lane & 3;
    const int j0 = 8 * warp + 2 * cc;
    float dx = 0.0f, dy = 0.0f;
#pragma unroll
    for (int k = 0; k < 13; k++) {
        float a = s_x[n][k];
        float2 w = *(const float2*)&W1s[k * 64 + j0];
        dx += a * w.x;
        dy += a * w.y;
    }
    float di = s_di[n];
    float zx = di * dx + b1s[j0];
    float zy = di * dy + b1s[j0 + 1];
    s_oh[n][4 * warp + cc] = __floats2half2_rn(di * fmaxf(zx, 0.0f),
                                               di * fmaxf(zy, 0.0f));
    __syncthreads();

    if (lane < 8) {
        __half2 u0 = s_oh[warp][4 * lane + 0];
        __half2 u1 = s_oh[warp][4 * lane + 1];
        __half2 u2 = s_oh[warp][4 * lane + 2];
        __half2 u3 = s_oh[warp][4 * lane + 3];
        int4 pack = make_int4(*(int*)&u0, *(int*)&u1, *(int*)&u2, *(int*)&u3);
        *reinterpret_cast<int4*>(g_x1h + v * 64 + lane * 8) = pack;
    }
}

// ---------------- 5. layer 2 (persistent; unchanged from round 8) ----------------
__global__ void k_layer2(const float* __restrict__ W2,
                         const float* __restrict__ b2,
                         const float* __restrict__ W3) {
    __shared__ float W2s[64 * 64];
    __shared__ float b2s[64];
    __shared__ float W3s[64 * 10];
    __shared__ float s_agg[8][68];
    __shared__ float s_x2[8][68];
    __shared__ __half2 s_x1h[8][33];
    __shared__ float s_di[8];

    for (int i = threadIdx.x; i < 64 * 64; i += 256) W2s[i] = W2[i];
    if (threadIdx.x < 64) b2s[threadIdx.x] = b2[threadIdx.x];
    for (int i = threadIdx.x; i < 64 * 10; i += 256) W3s[i] = W3[i];

    const int warp = threadIdx.x >> 5;
    const int lane = threadIdx.x & 31;
    const int sub = lane & 7, grp = lane >> 3;   // 8 lanes/edge, 4 edges/pass
    const int n = lane >> 2, cc = lane & 3;
    const int j0 = 8 * warp + 2 * cc;

    for (int gg = blockIdx.x; gg < NGRP; gg += PBLKS) {
        __syncthreads();
        const int v = gg * 8 + warp;

        float acc[8] = {0, 0, 0, 0, 0, 0, 0, 0};
        if (grp == 0) {
            const __half* self = g_x1h + v * 64 + sub * 8;
            acc8(acc, self);
            int4 raw = *reinterpret_cast<const int4*>(self);
            s_x1h[warp][sub * 4 + 0] = H2(raw.x);
            s_x1h[warp][sub * 4 + 1] = H2(raw.y);
            s_x1h[warp][sub * 4 + 2] = H2(raw.z);
            s_x1h[warp][sub * 4 + 3] = H2(raw.w);
        }
        int beg = g_rowptr[v], end = g_rowptr[v + 1];
        for (int t = beg; t < end; t += 16) {
            int i0 = t + grp, i1 = i0 + 4, i2 = i0 + 8, i3 = i0 + 12;
            int c0 = (i0 < end) ? g_col[i0] : ZROW;
            int c1 = (i1 < end) ? g_col[i1] : ZROW;
            int c2 = (i2 < end) ? g_col[i2] : ZROW;
            int c3 = (i3 < end) ? g_col[i3] : ZROW;
            int4 r0 = *(const int4*)(g_x1h + c0 * 64 + sub * 8);
            int4 r1 = *(const int4*)(g_x1h + c1 * 64 + sub * 8);
            int4 r2 = *(const int4*)(g_x1h + c2 * 64 + sub * 8);
            int4 r3 = *(const int4*)(g_x1h + c3 * 64 + sub * 8);
            acch(acc,
                 __hadd2(__hadd2(H2(r0.x), H2(r1.x)), __hadd2(H2(r2.x), H2(r3.x))),
                 __hadd2(__hadd2(H2(r0.y), H2(r1.y)), __hadd2(H2(r2.y), H2(r3.y))),
                 __hadd2(__hadd2(H2(r0.z), H2(r1.z)), __hadd2(H2(r2.z), H2(r3.z))),
                 __hadd2(__hadd2(H2(r0.w), H2(r1.w)), __hadd2(H2(r2.w), H2(r3.w))));
        }
#pragma unroll
        for (int off = 8; off <= 16; off <<= 1)
#pragma unroll
            for (int c = 0; c < 8; c++) acc[c] += __shfl_xor_sync(FULL, acc[c], off);
        if (lane < 8) {
#pragma unroll
            for (int c = 0; c < 8; c++) s_agg[warp][sub * 8 + c] = acc[c];
        }
        if (lane == 0) s_di[warp] = g_dinv[v];
        __syncthreads();

        // Phase B: x2 = relu(di*(agg@W2)+b2) + x1
        float dx = 0.0f, dy = 0.0f;
#pragma unroll
        for (int k4 = 0; k4 < 16; k4++) {
            float4 a = *(const float4*)&s_agg[n][4 * k4];
            float2 w0 = *(const float2*)&W2s[(4 * k4 + 0) * 64 + j0];
            float2 w1 = *(const float2*)&W2s[(4 * k4 + 1) * 64 + j0];
            float2 w2 = *(const float2*)&W2s[(4 * k4 + 2) * 64 + j0];
            float2 w3 = *(const float2*)&W2s[(4 * k4 + 3) * 64 + j0];
            dx += a.x * w0.x + a.y * w1.x + a.z * w2.x + a.w * w3.x;
            dy += a.x * w0.y + a.y * w1.y + a.z * w2.y + a.w * w3.y;
        }
        float di = s_di[n];
        float zx = di * dx + b2s[j0];
        float zy = di * dy + b2s[j0 + 1];
        float rdeg = 1.0f / di;
        float2 r = __half22float2(s_x1h[n][4 * warp + cc]);
        s_x2[n][j0]     = fmaxf(zx, 0.0f) + r.x * rdeg;
        s_x2[n][j0 + 1] = fmaxf(zy, 0.0f) + r.y * rdeg;
        __syncthreads();

        // Phase C: 80 threads compute the 80 (node, class) dots; p' = di*p
        if (threadIdx.x < 80) {
            int n2 = threadIdx.x / 10;
            int j  = threadIdx.x - n2 * 10;
            float p = 0.0f;
#pragma unroll
            for (int k4 = 0; k4 < 16; k4++) {
                float4 a = *(const float4*)&s_x2[n2][4 * k4];
                p += a.x * W3s[(4 * k4 + 0) * 10 + j]
                   + a.y * W3s[(4 * k4 + 1) * 10 + j]
                   + a.z * W3s[(4 * k4 + 2) * 10 + j]
                   + a.w * W3s[(4 * k4 + 3) * 10 + j];
            }
            g_ph[(gg * 8 + n2) * 16 + j] = __float2half(s_di[n2] * p);
        }
    }
}

// ---------------- 6. layer 3: 4 lanes/edge, 12-shfl reduction ----------------
__global__ void k_layer3(const float* __restrict__ b3, float* __restrict__ out) {
    __shared__ __align__(16) float sp[8][16];
    int warp = threadIdx.x >> 5;
    int v = blockIdx.x * 8 + warp;
    int lane = threadIdx.x & 31;
    int sub = lane & 3, grp = lane >> 2;   // 4 lanes/edge, 8 groups

    float acc[4] = {0, 0, 0, 0};
    if (grp == 0) {
        int2 raw = *(const int2*)(g_ph + v * 16 + sub * 4);
        acch4(acc, H2(raw.x), H2(raw.y));
    }
    int beg = g_rowptr[v], end = g_rowptr[v + 1];
    for (int t = beg; t < end; t += 16) {
        int i0 = t + grp, i1 = i0 + 8;
        int c0 = (i0 < end) ? g_col[i0] : ZROW;
        int c1 = (i1 < end) ? g_col[i1] : ZROW;
        int2 r0 = *(const int2*)(g_ph + c0 * 16 + sub * 4);
        int2 r1 = *(const int2*)(g_ph + c1 * 16 + sub * 4);
        acch4(acc, __hadd2(H2(r0.x), H2(r1.x)), __hadd2(H2(r0.y), H2(r1.y)));
    }
#pragma unroll
    for (int off = 4; off <= 16; off <<= 1)
#pragma unroll
        for (int c = 0; c < 4; c++) acc[c] += __shfl_xor_sync(FULL, acc[c], off);

    if (lane < 4)
        *(float4*)&sp[warp][lane * 4] = make_float4(acc[0], acc[1], acc[2], acc[3]);
    __syncwarp();

    float di = g_dinv[v];
    float z = (lane < 10) ? di * sp[warp][lane] + b3[lane] : -INFINITY;
    float mx = z;
    for (int off = 16; off; off >>= 1) mx = fmaxf(mx, __shfl_xor_sync(FULL, mx, off));
    float ex = (lane < 10) ? expf(z - mx) : 0.0f;
    float s = ex;
    for (int off = 16; off; off >>= 1) s += __shfl_xor_sync(FULL, s, off);
    if (lane < 10) out[v * 10 + lane] = z - mx - logf(s);
}

extern "C" void kernel_launch(void* const* d_in, const int* in_sizes, int n_in,
                              void* d_out, int out_size) {
    const float* x  = (const float*)d_in[0];
    const int*   ei = (const int*)d_in[1];
    const float* W1 = (const float*)d_in[2];
    const float* b1 = (const float*)d_in[3];
    const float* W2 = (const float*)d_in[4];
    const float* b2 = (const float*)d_in[5];
    const float* W3 = (const float*)d_in[6];
    const float* b3 = (const float*)d_in[7];
    float* out = (float*)d_out;

    const int TB = 256;
    int hist4Blocks = (N_EDGES / 4 + TB - 1) / TB;
    int scat2Blocks = (N_EDGES / 2 + TB - 1) / TB;

    k_hist<<<hist4Blocks, TB>>>(ei);
    k_scanfused<<<NB_SCAN, TB>>>(x);
    k_scatter<<<scat2Blocks, TB>>>(ei);
    k_layer1<<<NGRP, TB>>>(W1, b1);
    k_layer2<<<PBLKS, TB>>>(W2, b2, W3);
    k_layer3<<<NGRP, TB>>>(b3, out);
}